// round 3
// baseline (speedup 1.0000x reference)
#include <cuda_runtime.h>
#include <math.h>

#define BB   64
#define SS   2048
#define EH   512
#define AH   512

#define TM   64
#define TA   64
#define TK   32

// scratch (no allocations allowed)
__device__ float g_dec_proj[BB * AH];
__device__ float g_score[BB * SS];

// ---------------------------------------------------------------------------
// K1: dec_proj[b,a] = sum_d dec_hidden[b,d] * W_dec[a,d]
// ---------------------------------------------------------------------------
__global__ void dec_proj_kernel(const float* __restrict__ dec_hidden,
                                const float* __restrict__ W_dec) {
    int b = blockIdx.x;
    __shared__ float sh[EH];
    for (int i = threadIdx.x; i < EH; i += blockDim.x)
        sh[i] = dec_hidden[b * EH + i];
    __syncthreads();

    int warp = threadIdx.x >> 5;
    int lane = threadIdx.x & 31;
    int nwarp = blockDim.x >> 5;
    for (int a = warp; a < AH; a += nwarp) {
        const float* wr = W_dec + (size_t)a * EH;
        float acc = 0.f;
        #pragma unroll 4
        for (int d = lane; d < EH; d += 32)
            acc += sh[d] * wr[d];
        #pragma unroll
        for (int o = 16; o > 0; o >>= 1)
            acc += __shfl_xor_sync(0xffffffffu, acc, o);
        if (lane == 0) g_dec_proj[b * AH + a] = acc;
    }
}

// ---------------------------------------------------------------------------
// K2: fused score kernel.
//   score[b,s] = sum_a tanh(enc_proj[b,s,a] + dec_proj[b,a]) * v[a]
// 64x64 output tile per block, 4x4 register tile per thread, K staged in smem.
// Global->smem loads vectorized as float4 (rows are 2KB-aligned, k0 is a
// multiple of 32 floats, so 16B alignment always holds).
// ---------------------------------------------------------------------------
__global__ void __launch_bounds__(256) score_kernel(
        const float* __restrict__ enc,
        const float* __restrict__ Wenc,
        const float* __restrict__ v) {
    const int b  = blockIdx.y;
    const int s0 = blockIdx.x * TM;
    const int tx = threadIdx.x & 15;   // a dimension (16 lanes * 4)
    const int ty = threadIdx.x >> 4;   // m dimension (16 * 4)

    __shared__ float As[TK][TM + 1];   // [k][m]
    __shared__ float Bs[TK][TA + 1];   // [k][a]
    __shared__ float sv[TA];
    __shared__ float sdec[TA];
    __shared__ float red[TM][17];

    const float* encb = enc + ((size_t)b * SS + s0) * EH;

    float score_acc[4] = {0.f, 0.f, 0.f, 0.f};

    for (int a0 = 0; a0 < AH; a0 += TA) {
        __syncthreads();               // protect sv/sdec from prior epilogue
        if (threadIdx.x < TA) {
            sv[threadIdx.x]   = v[a0 + threadIdx.x];
            sdec[threadIdx.x] = g_dec_proj[b * AH + a0 + threadIdx.x];
        }

        float acc[4][4];
        #pragma unroll
        for (int i = 0; i < 4; i++)
            #pragma unroll
            for (int j = 0; j < 4; j++) acc[i][j] = 0.f;

        for (int k0 = 0; k0 < EH; k0 += TK) {
            // load enc tile [TM x TK] -> As[k][m], float4 per thread.
            // TM*TK/4 = 512 float4s; 256 threads -> 2 each.
            #pragma unroll
            for (int i = threadIdx.x; i < TM * TK / 4; i += 256) {
                int m  = i >> 3;       // / (TK/4)
                int k4 = i & 7;        // % (TK/4)
                float4 val = *(const float4*)&encb[(size_t)m * EH + k0 + k4 * 4];
                As[k4 * 4 + 0][m] = val.x;
                As[k4 * 4 + 1][m] = val.y;
                As[k4 * 4 + 2][m] = val.z;
                As[k4 * 4 + 3][m] = val.w;
            }
            // load W tile [TA x TK] -> Bs[k][a], float4 per thread.
            #pragma unroll
            for (int i = threadIdx.x; i < TA * TK / 4; i += 256) {
                int a  = i >> 3;
                int k4 = i & 7;
                float4 val = *(const float4*)&Wenc[(size_t)(a0 + a) * EH + k0 + k4 * 4];
                Bs[k4 * 4 + 0][a] = val.x;
                Bs[k4 * 4 + 1][a] = val.y;
                Bs[k4 * 4 + 2][a] = val.z;
                Bs[k4 * 4 + 3][a] = val.w;
            }
            __syncthreads();

            #pragma unroll
            for (int k = 0; k < TK; k++) {
                float ra[4], rb[4];
                #pragma unroll
                for (int i = 0; i < 4; i++) ra[i] = As[k][ty * 4 + i];
                #pragma unroll
                for (int j = 0; j < 4; j++) rb[j] = Bs[k][tx * 4 + j];
                #pragma unroll
                for (int i = 0; i < 4; i++)
                    #pragma unroll
                    for (int j = 0; j < 4; j++)
                        acc[i][j] = fmaf(ra[i], rb[j], acc[i][j]);
            }
            __syncthreads();
        }

        // epilogue: tanh(enc_proj + dec_proj) * v, accumulate over a
        #pragma unroll
        for (int i = 0; i < 4; i++) {
            #pragma unroll
            for (int j = 0; j < 4; j++) {
                int la = tx * 4 + j;
                float x2 = 2.f * (acc[i][j] + sdec[la]);
                x2 = fminf(fmaxf(x2, -30.f), 30.f);
                float e = __expf(x2);
                float t = __fdividef(e - 1.f, e + 1.f);
                score_acc[i] += t * sv[la];
            }
        }
    }

    // reduce across the 16 tx lanes per row
    __syncthreads();
    #pragma unroll
    for (int i = 0; i < 4; i++)
        red[ty * 4 + i][tx] = score_acc[i];
    __syncthreads();

    if (threadIdx.x < TM) {
        float s = 0.f;
        #pragma unroll
        for (int t = 0; t < 16; t++) s += red[threadIdx.x][t];
        g_score[b * SS + s0 + threadIdx.x] = s;
    }
}

// ---------------------------------------------------------------------------
// K3: softmax over S per batch row. weights -> d_out + B*EH
// ---------------------------------------------------------------------------
__global__ void __launch_bounds__(256) softmax_kernel(float* __restrict__ out_w) {
    const int b   = blockIdx.x;
    const int tid = threadIdx.x;
    __shared__ float sred[32];

    float vals[8];
    float vmax = -1e30f;
    #pragma unroll
    for (int i = 0; i < 8; i++) {
        vals[i] = g_score[b * SS + tid + i * 256];
        vmax = fmaxf(vmax, vals[i]);
    }
    // block max
    #pragma unroll
    for (int o = 16; o > 0; o >>= 1)
        vmax = fmaxf(vmax, __shfl_xor_sync(0xffffffffu, vmax, o));
    if ((tid & 31) == 0) sred[tid >> 5] = vmax;
    __syncthreads();
    float bmax = sred[0];
    #pragma unroll
    for (int w = 1; w < 8; w++) bmax = fmaxf(bmax, sred[w]);

    float vsum = 0.f;
    #pragma unroll
    for (int i = 0; i < 8; i++) {
        vals[i] = expf(vals[i] - bmax);
        vsum += vals[i];
    }
    #pragma unroll
    for (int o = 16; o > 0; o >>= 1)
        vsum += __shfl_xor_sync(0xffffffffu, vsum, o);
    __syncthreads();
    if ((tid & 31) == 0) sred[tid >> 5] = vsum;
    __syncthreads();
    float bsum = 0.f;
    #pragma unroll
    for (int w = 0; w < 8; w++) bsum += sred[w];

    float inv = __frcp_rn(bsum);
    #pragma unroll
    for (int i = 0; i < 8; i++)
        out_w[b * SS + tid + i * 256] = vals[i] * inv;
}

// ---------------------------------------------------------------------------
// K4: context[b,e] = sum_s w[b,s] * enc[b,s,e]
// ---------------------------------------------------------------------------
__global__ void __launch_bounds__(128) context_kernel(
        const float* __restrict__ enc,
        const float* __restrict__ w,     // d_out + B*EH
        float* __restrict__ ctx) {       // d_out
    const int b  = blockIdx.y;
    const int e  = blockIdx.x * 128 + threadIdx.x;
    const float* encb = enc + (size_t)b * SS * EH + e;
    const float* wb = w + b * SS;

    float acc0 = 0.f, acc1 = 0.f, acc2 = 0.f, acc3 = 0.f;
    #pragma unroll 2
    for (int s = 0; s < SS; s += 4) {
        acc0 += wb[s + 0] * encb[(size_t)(s + 0) * EH];
        acc1 += wb[s + 1] * encb[(size_t)(s + 1) * EH];
        acc2 += wb[s + 2] * encb[(size_t)(s + 2) * EH];
        acc3 += wb[s + 3] * encb[(size_t)(s + 3) * EH];
    }
    ctx[b * EH + e] = ((acc0 + acc1) + (acc2 + acc3));
}

// ---------------------------------------------------------------------------
extern "C" void kernel_launch(void* const* d_in, const int* in_sizes, int n_in,
                              void* d_out, int out_size) {
    const float* enc   = (const float*)d_in[0];  // [B,S,EH]
    const float* dec   = (const float*)d_in[1];  // [B,EH]
    const float* W_enc = (const float*)d_in[2];  // [AH,EH]
    const float* W_dec = (const float*)d_in[3];  // [AH,EH]
    const float* v     = (const float*)d_in[4];  // [1,AH]

    float* out = (float*)d_out;
    float* out_ctx = out;                 // [B, EH]
    float* out_w   = out + BB * EH;       // [B, S]

    dec_proj_kernel<<<BB, 256>>>(dec, W_dec);

    dim3 g2(SS / TM, BB);
    score_kernel<<<g2, 256>>>(enc, W_enc, v);

    softmax_kernel<<<BB, 256>>>(out_w);

    dim3 g4(EH / 128, BB);
    context_kernel<<<g4, 128>>>(enc, out_w, out_ctx);
}

// round 4
// speedup vs baseline: 3.6633x; 3.6633x over previous
#include <cuda_runtime.h>
#include <math.h>
#include <stdint.h>

#define BB   64
#define SS   2048
#define EH   512
#define AH   512

#define SPLITS 16
#define SCH    (SS / SPLITS)    // 128

// scratch (no allocations allowed)
__device__ float g_dec_proj[BB * AH];
__device__ float g_score[BB * SS];
__device__ float g_ctx_part[SPLITS * BB * EH];

// ---------------------------------------------------------------------------
__device__ __forceinline__ uint32_t f2tf32(float x) {
    uint32_t r;
    asm("cvt.rna.tf32.f32 %0, %1;" : "=r"(r) : "f"(x));
    return r;
}

__device__ __forceinline__ float fast_tanh(float x) {
    float y;
    asm("tanh.approx.f32 %0, %1;" : "=f"(y) : "f"(x));
    return y;
}

__device__ __forceinline__ void mma_tf32(float* c, const uint32_t* a, const uint32_t* b) {
    asm volatile(
        "mma.sync.aligned.m16n8k8.row.col.f32.tf32.tf32.f32 "
        "{%0,%1,%2,%3}, {%4,%5,%6,%7}, {%8,%9}, {%0,%1,%2,%3};\n"
        : "+f"(c[0]), "+f"(c[1]), "+f"(c[2]), "+f"(c[3])
        : "r"(a[0]), "r"(a[1]), "r"(a[2]), "r"(a[3]),
          "r"(b[0]), "r"(b[1]));
}

// ---------------------------------------------------------------------------
// K1: dec_proj[b,a] = sum_d dec_hidden[b,d] * W_dec[a,d]
// ---------------------------------------------------------------------------
__global__ void dec_proj_kernel(const float* __restrict__ dec_hidden,
                                const float* __restrict__ W_dec) {
    int b = blockIdx.x;
    __shared__ float sh[EH];
    for (int i = threadIdx.x; i < EH; i += blockDim.x)
        sh[i] = dec_hidden[b * EH + i];
    __syncthreads();

    int warp = threadIdx.x >> 5;
    int lane = threadIdx.x & 31;
    int nwarp = blockDim.x >> 5;
    for (int a = warp; a < AH; a += nwarp) {
        const float* wr = W_dec + (size_t)a * EH;
        float acc = 0.f;
        #pragma unroll 4
        for (int d = lane; d < EH; d += 32)
            acc += sh[d] * wr[d];
        #pragma unroll
        for (int o = 16; o > 0; o >>= 1)
            acc += __shfl_xor_sync(0xffffffffu, acc, o);
        if (lane == 0) g_dec_proj[b * AH + a] = acc;
    }
}

// ---------------------------------------------------------------------------
// K2: fused score kernel on tensor cores (tf32 mma.sync m16n8k8).
//   score[b,s] = sum_a tanh(enc_proj[b,s,a] + dec_proj[b,a]) * v[a]
// CTA tile: 128 (s) x 128 (a per iter), 4 a-iters.  8 warps = 2(m) x 4(n),
// warp tile 64x32. K staged in smem chunks of 32 with register prefetch.
// ---------------------------------------------------------------------------
#define KT    32
#define NKCH  (EH / KT)   // 16
#define APAD  36          // smem row stride (words) -> conflict-free frags

__global__ void __launch_bounds__(256, 1) score_kernel(
        const float* __restrict__ enc,
        const float* __restrict__ Wenc,
        const float* __restrict__ v) {
    const int b  = blockIdx.y;
    const int s0 = blockIdx.x * 128;
    const int tid = threadIdx.x;
    const int wid = tid >> 5;
    const int lane = tid & 31;
    const int g = lane >> 2;      // group
    const int t = lane & 3;       // thread-in-group
    const int warp_m = (wid & 1) * 64;
    const int warp_n = (wid >> 1) * 32;
    const int wn_idx = wid >> 1;

    __shared__ uint32_t As[128 * APAD];
    __shared__ uint32_t Bs[128 * APAD];
    __shared__ float sv[128];
    __shared__ float sdec[128];
    __shared__ float sscore[128];
    __shared__ float red[128 * 4];

    const float* encb = enc + ((size_t)b * SS + s0) * EH;

    if (tid < 128) sscore[tid] = 0.f;

    for (int a0 = 0; a0 < AH; a0 += 128) {
        const float* wb = Wenc + (size_t)a0 * EH;

        // stage sv / sdec for this a-chunk (epilogue-end sync of previous
        // iter guarantees the old values are no longer being read)
        if (tid < 128) {
            sv[tid]   = v[a0 + tid];
            sdec[tid] = g_dec_proj[b * AH + a0 + tid];
        }

        float acc[4][4][4];
        #pragma unroll
        for (int mf = 0; mf < 4; mf++)
            #pragma unroll
            for (int nf = 0; nf < 4; nf++)
                #pragma unroll
                for (int cc = 0; cc < 4; cc++) acc[mf][nf][cc] = 0.f;

        // ---- prologue: load chunk 0 into regs, store to smem ----
        float4 ra[4], rb[4];
        {
            #pragma unroll
            for (int j = 0; j < 4; j++) {
                int i = tid + j * 256;
                int m = i >> 3, k4 = i & 7;
                ra[j] = *(const float4*)&encb[(size_t)m * EH + k4 * 4];
                rb[j] = *(const float4*)&wb  [(size_t)m * EH + k4 * 4];
            }
        }
        __syncthreads();   // all prior smem reads (prev iter) complete
        #pragma unroll
        for (int j = 0; j < 4; j++) {
            int i = tid + j * 256;
            int m = i >> 3, k4 = i & 7;
            uint4 va = make_uint4(f2tf32(ra[j].x), f2tf32(ra[j].y),
                                  f2tf32(ra[j].z), f2tf32(ra[j].w));
            uint4 vb = make_uint4(f2tf32(rb[j].x), f2tf32(rb[j].y),
                                  f2tf32(rb[j].z), f2tf32(rb[j].w));
            *(uint4*)&As[m * APAD + k4 * 4] = va;
            *(uint4*)&Bs[m * APAD + k4 * 4] = vb;
        }
        __syncthreads();

        // ---- main K loop ----
        for (int chunk = 0; chunk < NKCH; chunk++) {
            // prefetch next chunk into regs while doing mma on current
            if (chunk + 1 < NKCH) {
                int k0 = (chunk + 1) * KT;
                #pragma unroll
                for (int j = 0; j < 4; j++) {
                    int i = tid + j * 256;
                    int m = i >> 3, k4 = i & 7;
                    ra[j] = *(const float4*)&encb[(size_t)m * EH + k0 + k4 * 4];
                    rb[j] = *(const float4*)&wb  [(size_t)m * EH + k0 + k4 * 4];
                }
            }

            #pragma unroll
            for (int kk = 0; kk < KT; kk += 8) {
                uint32_t af[4][4];
                #pragma unroll
                for (int mf = 0; mf < 4; mf++) {
                    int r = warp_m + mf * 16 + g;
                    af[mf][0] = As[(r)     * APAD + kk + t];
                    af[mf][1] = As[(r + 8) * APAD + kk + t];
                    af[mf][2] = As[(r)     * APAD + kk + t + 4];
                    af[mf][3] = As[(r + 8) * APAD + kk + t + 4];
                }
                uint32_t bf[4][2];
                #pragma unroll
                for (int nf = 0; nf < 4; nf++) {
                    int c = warp_n + nf * 8 + g;
                    bf[nf][0] = Bs[c * APAD + kk + t];
                    bf[nf][1] = Bs[c * APAD + kk + t + 4];
                }
                #pragma unroll
                for (int mf = 0; mf < 4; mf++)
                    #pragma unroll
                    for (int nf = 0; nf < 4; nf++)
                        mma_tf32(acc[mf][nf], af[mf], bf[nf]);
            }

            if (chunk + 1 < NKCH) {
                __syncthreads();   // everyone done reading current tile
                #pragma unroll
                for (int j = 0; j < 4; j++) {
                    int i = tid + j * 256;
                    int m = i >> 3, k4 = i & 7;
                    uint4 va = make_uint4(f2tf32(ra[j].x), f2tf32(ra[j].y),
                                          f2tf32(ra[j].z), f2tf32(ra[j].w));
                    uint4 vb = make_uint4(f2tf32(rb[j].x), f2tf32(rb[j].y),
                                          f2tf32(rb[j].z), f2tf32(rb[j].w));
                    *(uint4*)&As[m * APAD + k4 * 4] = va;
                    *(uint4*)&Bs[m * APAD + k4 * 4] = vb;
                }
                __syncthreads();
            }
        }

        // ---- epilogue: tanh(acc + dec) * v, reduce over the 128 a-cols ----
        float rowsum[4][2];
        #pragma unroll
        for (int mf = 0; mf < 4; mf++) { rowsum[mf][0] = 0.f; rowsum[mf][1] = 0.f; }

        #pragma unroll
        for (int mf = 0; mf < 4; mf++) {
            #pragma unroll
            for (int nf = 0; nf < 4; nf++) {
                int nbase = warp_n + nf * 8 + t * 2;
                #pragma unroll
                for (int cc = 0; cc < 4; cc++) {
                    int n = nbase + (cc & 1);
                    float x = acc[mf][nf][cc] + sdec[n];
                    rowsum[mf][cc >> 1] += fast_tanh(x) * sv[n];
                }
            }
        }
        // reduce across the 4 t-lanes (same rows, different n)
        #pragma unroll
        for (int mf = 0; mf < 4; mf++) {
            #pragma unroll
            for (int o = 0; o < 2; o++) {
                rowsum[mf][o] += __shfl_xor_sync(0xffffffffu, rowsum[mf][o], 1);
                rowsum[mf][o] += __shfl_xor_sync(0xffffffffu, rowsum[mf][o], 2);
            }
        }
        if (t == 0) {
            #pragma unroll
            for (int mf = 0; mf < 4; mf++) {
                red[(warp_m + mf * 16 + g)     * 4 + wn_idx] = rowsum[mf][0];
                red[(warp_m + mf * 16 + g + 8) * 4 + wn_idx] = rowsum[mf][1];
            }
        }
        __syncthreads();
        if (tid < 128) {
            float4 rr = *(const float4*)&red[tid * 4];
            sscore[tid] += (rr.x + rr.y) + (rr.z + rr.w);
        }
        __syncthreads();   // end-of-iter barrier (protects sv/sdec/red reuse)
    }

    if (tid < 128)
        g_score[b * SS + s0 + tid] = sscore[tid];
}

// ---------------------------------------------------------------------------
// K3: softmax over S per batch row. weights -> d_out + B*EH
// ---------------------------------------------------------------------------
__global__ void __launch_bounds__(256) softmax_kernel(float* __restrict__ out_w) {
    const int b   = blockIdx.x;
    const int tid = threadIdx.x;
    __shared__ float sred[32];

    float vals[8];
    float vmax = -1e30f;
    #pragma unroll
    for (int i = 0; i < 8; i++) {
        vals[i] = g_score[b * SS + tid + i * 256];
        vmax = fmaxf(vmax, vals[i]);
    }
    #pragma unroll
    for (int o = 16; o > 0; o >>= 1)
        vmax = fmaxf(vmax, __shfl_xor_sync(0xffffffffu, vmax, o));
    if ((tid & 31) == 0) sred[tid >> 5] = vmax;
    __syncthreads();
    float bmax = sred[0];
    #pragma unroll
    for (int w = 1; w < 8; w++) bmax = fmaxf(bmax, sred[w]);

    float vsum = 0.f;
    #pragma unroll
    for (int i = 0; i < 8; i++) {
        vals[i] = expf(vals[i] - bmax);
        vsum += vals[i];
    }
    #pragma unroll
    for (int o = 16; o > 0; o >>= 1)
        vsum += __shfl_xor_sync(0xffffffffu, vsum, o);
    __syncthreads();
    if ((tid & 31) == 0) sred[tid >> 5] = vsum;
    __syncthreads();
    float bsum = 0.f;
    #pragma unroll
    for (int w = 0; w < 8; w++) bsum += sred[w];

    float inv = __frcp_rn(bsum);
    #pragma unroll
    for (int i = 0; i < 8; i++)
        out_w[b * SS + tid + i * 256] = vals[i] * inv;
}

// ---------------------------------------------------------------------------
// K4a: partial context over an S-chunk:
//      g_ctx_part[sp, b, e] = sum_{s in chunk sp} w[b,s] * enc[b,s,e]
// ---------------------------------------------------------------------------
__global__ void __launch_bounds__(128) context_partial_kernel(
        const float* __restrict__ enc,
        const float* __restrict__ w) {
    const int b  = blockIdx.x;
    const int sp = blockIdx.y;
    const int e4 = threadIdx.x << 2;

    const float* wb   = w + b * SS + sp * SCH;
    const float* encb = enc + ((size_t)b * SS + (size_t)sp * SCH) * EH + e4;

    float4 acc = make_float4(0.f, 0.f, 0.f, 0.f);
    #pragma unroll 4
    for (int s = 0; s < SCH; s++) {
        float ws = wb[s];
        float4 ev = *(const float4*)(encb + (size_t)s * EH);
        acc.x += ws * ev.x;
        acc.y += ws * ev.y;
        acc.z += ws * ev.z;
        acc.w += ws * ev.w;
    }
    *(float4*)&g_ctx_part[((size_t)sp * BB + b) * EH + e4] = acc;
}

// ---------------------------------------------------------------------------
// K4b: deterministic reduce of the SPLITS partials into ctx (d_out)
// ---------------------------------------------------------------------------
__global__ void __launch_bounds__(256) context_reduce_kernel(float* __restrict__ ctx) {
    const int i = blockIdx.x * 256 + threadIdx.x;   // 0 .. BB*EH-1
    float s = 0.f;
    #pragma unroll
    for (int sp = 0; sp < SPLITS; sp++)
        s += g_ctx_part[(size_t)sp * BB * EH + i];
    ctx[i] = s;
}

// ---------------------------------------------------------------------------
extern "C" void kernel_launch(void* const* d_in, const int* in_sizes, int n_in,
                              void* d_out, int out_size) {
    const float* enc   = (const float*)d_in[0];  // [B,S,EH]
    const float* dec   = (const float*)d_in[1];  // [B,EH]
    const float* W_enc = (const float*)d_in[2];  // [AH,EH]
    const float* W_dec = (const float*)d_in[3];  // [AH,EH]
    const float* v     = (const float*)d_in[4];  // [1,AH]

    float* out = (float*)d_out;
    float* out_ctx = out;                 // [B, EH]
    float* out_w   = out + BB * EH;       // [B, S]

    dec_proj_kernel<<<BB, 256>>>(dec, W_dec);

    dim3 g2(SS / 128, BB);
    score_kernel<<<g2, 256>>>(enc, W_enc, v);

    softmax_kernel<<<BB, 256>>>(out_w);

    dim3 g4(BB, SPLITS);
    context_partial_kernel<<<g4, 128>>>(enc, out_w);

    context_reduce_kernel<<<(BB * EH) / 256, 256>>>(out_ctx);
}

// round 6
// speedup vs baseline: 3.8201x; 1.0428x over previous
#include <cuda_runtime.h>
#include <math.h>
#include <stdint.h>

#define BB   64
#define SS   2048
#define EH   512
#define AH   512

#define SPLITS 32
#define SCH    (SS / SPLITS)    // 64

// scratch (no allocations allowed)
__device__ float g_dec_proj[BB * AH];
__device__ float g_score[BB * SS];
__device__ float g_ctx_part[SPLITS * BB * EH];

// ---------------------------------------------------------------------------
__device__ __forceinline__ uint32_t f2tf32(float x) {
    uint32_t r;
    asm("cvt.rna.tf32.f32 %0, %1;" : "=r"(r) : "f"(x));
    return r;
}
__device__ __forceinline__ float fast_tanh(float x) {
    float y; asm("tanh.approx.f32 %0, %1;" : "=f"(y) : "f"(x)); return y;
}
__device__ __forceinline__ void mma_tf32(float* c, const uint32_t* a, const uint32_t* b) {
    asm volatile(
        "mma.sync.aligned.m16n8k8.row.col.f32.tf32.tf32.f32 "
        "{%0,%1,%2,%3}, {%4,%5,%6,%7}, {%8,%9}, {%0,%1,%2,%3};\n"
        : "+f"(c[0]), "+f"(c[1]), "+f"(c[2]), "+f"(c[3])
        : "r"(a[0]), "r"(a[1]), "r"(a[2]), "r"(a[3]),
          "r"(b[0]), "r"(b[1]));
}

// ---------------------------------------------------------------------------
// K1: dec_proj[b,a] = sum_d dec_hidden[b,d] * W_dec[a,d]
// ---------------------------------------------------------------------------
__global__ void dec_proj_kernel(const float* __restrict__ dec_hidden,
                                const float* __restrict__ W_dec) {
    int b = blockIdx.x;
    __shared__ float sh[EH];
    for (int i = threadIdx.x; i < EH; i += blockDim.x)
        sh[i] = dec_hidden[b * EH + i];
    __syncthreads();

    int warp = threadIdx.x >> 5;
    int lane = threadIdx.x & 31;
    int nwarp = blockDim.x >> 5;
    for (int a = warp; a < AH; a += nwarp) {
        const float* wr = W_dec + (size_t)a * EH;
        float acc = 0.f;
        #pragma unroll 4
        for (int d = lane; d < EH; d += 32)
            acc += sh[d] * wr[d];
        #pragma unroll
        for (int o = 16; o > 0; o >>= 1)
            acc += __shfl_xor_sync(0xffffffffu, acc, o);
        if (lane == 0) g_dec_proj[b * AH + a] = acc;
    }
}

// ---------------------------------------------------------------------------
// K2: fused score kernel (tf32 mma.sync m16n8k8), frag-major smem layout.
//   score[b,s] = sum_a tanh(enc_proj[b,s,a] + dec_proj[b,a]) * v[a]
// CTA tile 128(s) x 128(a) x KT=32 chunks; 8 warps = 2(m) x 4(n), warp 64x32.
// A fragments read as LDS.128, B as LDS.64 (layout stores mma fragment order).
// ---------------------------------------------------------------------------
#define KT     32
#define NKCH   (EH / KT)   // 16
#define AW_PAD 1028        // words per A kb-tile (1024 + 4 pad, 16B aligned)
#define BW_PAD 1026        // words per B kb-tile (1024 + 2 pad, 8B aligned)

__global__ void __launch_bounds__(256, 1) score_kernel(
        const float* __restrict__ enc,
        const float* __restrict__ Wenc,
        const float* __restrict__ v) {
    const int b  = blockIdx.y;
    const int s0 = blockIdx.x * 128;
    const int tid = threadIdx.x;
    const int wid = tid >> 5;
    const int lane = tid & 31;
    const int g = lane >> 2;      // group (row-in-8 / col-in-8)
    const int t = lane & 3;       // thread-in-group (k)
    const int warp_m = (wid & 1) * 64;
    const int warp_n = (wid >> 1) * 32;
    const int wn_idx = wid >> 1;

    __shared__ uint32_t As[4 * AW_PAD];   // frag-major, per kb tile
    __shared__ uint32_t Bs[4 * BW_PAD];
    __shared__ float sv[128];
    __shared__ float sdec[128];
    __shared__ float sscore[128];
    __shared__ float red[128 * 4];

    const float* encb = enc + ((size_t)b * SS + s0) * EH;

    if (tid < 128) sscore[tid] = 0.f;

    for (int a0 = 0; a0 < AH; a0 += 128) {
        const float* wb = Wenc + (size_t)a0 * EH;

        if (tid < 128) {
            sv[tid]   = v[a0 + tid];
            sdec[tid] = g_dec_proj[b * AH + a0 + tid];
        }

        float acc[4][4][4];
        #pragma unroll
        for (int mf = 0; mf < 4; mf++)
            #pragma unroll
            for (int nf = 0; nf < 4; nf++)
                #pragma unroll
                for (int cc = 0; cc < 4; cc++) acc[mf][nf][cc] = 0.f;

        // ---- prologue: load chunk 0 into regs ----
        float4 ra[4], rb[4];
        #pragma unroll
        for (int j = 0; j < 4; j++) {
            int i = tid + j * 256;
            int m = i >> 3, k4 = i & 7;
            ra[j] = *(const float4*)&encb[(size_t)m * EH + k4 * 4];
            rb[j] = *(const float4*)&wb  [(size_t)m * EH + k4 * 4];
        }
        __syncthreads();
        #pragma unroll
        for (int j = 0; j < 4; j++) {
            int i = tid + j * 256;
            int m = i >> 3, k4 = i & 7;
            int kb = k4 >> 1, khigh = k4 & 1;
            // A: frag-major slot
            {
                int mb = m >> 4, gg = m & 7, rh = (m >> 3) & 1;
                int base = kb * AW_PAD + mb * 128 + khigh * 2 + rh;
                const float* f = &ra[j].x;
                #pragma unroll
                for (int c = 0; c < 4; c++)
                    As[base + (gg * 4 + c) * 4] = f2tf32(f[c]);
            }
            // B: frag-major slot
            {
                int nb = m >> 3, gg = m & 7;
                int base = kb * BW_PAD + nb * 64 + khigh;
                const float* f = &rb[j].x;
                #pragma unroll
                for (int c = 0; c < 4; c++)
                    Bs[base + (gg * 4 + c) * 2] = f2tf32(f[c]);
            }
        }
        __syncthreads();

        // ---- main K loop ----
        for (int chunk = 0; chunk < NKCH; chunk++) {
            if (chunk + 1 < NKCH) {
                int k0 = (chunk + 1) * KT;
                #pragma unroll
                for (int j = 0; j < 4; j++) {
                    int i = tid + j * 256;
                    int m = i >> 3, k4 = i & 7;
                    ra[j] = *(const float4*)&encb[(size_t)m * EH + k0 + k4 * 4];
                    rb[j] = *(const float4*)&wb  [(size_t)m * EH + k0 + k4 * 4];
                }
            }

            #pragma unroll
            for (int kb = 0; kb < 4; kb++) {
                uint4 af[4];
                #pragma unroll
                for (int mf = 0; mf < 4; mf++) {
                    int mb = (wid & 1) * 4 + mf;
                    af[mf] = *(const uint4*)&As[kb * AW_PAD + mb * 128 + lane * 4];
                }
                uint2 bf[4];
                #pragma unroll
                for (int nf = 0; nf < 4; nf++) {
                    int nb = (wid >> 1) * 4 + nf;
                    bf[nf] = *(const uint2*)&Bs[kb * BW_PAD + nb * 64 + lane * 2];
                }
                #pragma unroll
                for (int mf = 0; mf < 4; mf++)
                    #pragma unroll
                    for (int nf = 0; nf < 4; nf++)
                        mma_tf32(acc[mf][nf], (const uint32_t*)&af[mf],
                                 (const uint32_t*)&bf[nf]);
            }

            if (chunk + 1 < NKCH) {
                __syncthreads();
                #pragma unroll
                for (int j = 0; j < 4; j++) {
                    int i = tid + j * 256;
                    int m = i >> 3, k4 = i & 7;
                    int kb = k4 >> 1, khigh = k4 & 1;
                    {
                        int mb = m >> 4, gg = m & 7, rh = (m >> 3) & 1;
                        int base = kb * AW_PAD + mb * 128 + khigh * 2 + rh;
                        const float* f = &ra[j].x;
                        #pragma unroll
                        for (int c = 0; c < 4; c++)
                            As[base + (gg * 4 + c) * 4] = f2tf32(f[c]);
                    }
                    {
                        int nb = m >> 3, gg = m & 7;
                        int base = kb * BW_PAD + nb * 64 + khigh;
                        const float* f = &rb[j].x;
                        #pragma unroll
                        for (int c = 0; c < 4; c++)
                            Bs[base + (gg * 4 + c) * 2] = f2tf32(f[c]);
                    }
                }
                __syncthreads();
            }
        }

        // ---- epilogue: tanh(acc + dec) * v, reduce over the 128 a-cols ----
        float rowsum[4][2];
        #pragma unroll
        for (int mf = 0; mf < 4; mf++) { rowsum[mf][0] = 0.f; rowsum[mf][1] = 0.f; }

        #pragma unroll
        for (int mf = 0; mf < 4; mf++) {
            #pragma unroll
            for (int nf = 0; nf < 4; nf++) {
                int nbase = warp_n + nf * 8 + t * 2;
                #pragma unroll
                for (int cc = 0; cc < 4; cc++) {
                    int n = nbase + (cc & 1);
                    float x = acc[mf][nf][cc] + sdec[n];
                    rowsum[mf][cc >> 1] += fast_tanh(x) * sv[n];
                }
            }
        }
        #pragma unroll
        for (int mf = 0; mf < 4; mf++) {
            #pragma unroll
            for (int o = 0; o < 2; o++) {
                rowsum[mf][o] += __shfl_xor_sync(0xffffffffu, rowsum[mf][o], 1);
                rowsum[mf][o] += __shfl_xor_sync(0xffffffffu, rowsum[mf][o], 2);
            }
        }
        if (t == 0) {
            #pragma unroll
            for (int mf = 0; mf < 4; mf++) {
                red[(warp_m + mf * 16 + g)     * 4 + wn_idx] = rowsum[mf][0];
                red[(warp_m + mf * 16 + g + 8) * 4 + wn_idx] = rowsum[mf][1];
            }
        }
        __syncthreads();
        if (tid < 128) {
            float4 rr = *(const float4*)&red[tid * 4];
            sscore[tid] += (rr.x + rr.y) + (rr.z + rr.w);
        }
        __syncthreads();
    }

    if (tid < 128)
        g_score[b * SS + s0 + tid] = sscore[tid];
}

// ---------------------------------------------------------------------------
// K3: softmax over S per batch row. weights -> d_out + B*EH
// ---------------------------------------------------------------------------
__global__ void __launch_bounds__(256) softmax_kernel(float* __restrict__ out_w) {
    const int b   = blockIdx.x;
    const int tid = threadIdx.x;
    __shared__ float sred[32];

    float vals[8];
    float vmax = -1e30f;
    #pragma unroll
    for (int i = 0; i < 8; i++) {
        vals[i] = g_score[b * SS + tid + i * 256];
        vmax = fmaxf(vmax, vals[i]);
    }
    #pragma unroll
    for (int o = 16; o > 0; o >>= 1)
        vmax = fmaxf(vmax, __shfl_xor_sync(0xffffffffu, vmax, o));
    if ((tid & 31) == 0) sred[tid >> 5] = vmax;
    __syncthreads();
    float bmax = sred[0];
    #pragma unroll
    for (int w = 1; w < 8; w++) bmax = fmaxf(bmax, sred[w]);

    float vsum = 0.f;
    #pragma unroll
    for (int i = 0; i < 8; i++) {
        vals[i] = expf(vals[i] - bmax);
        vsum += vals[i];
    }
    #pragma unroll
    for (int o = 16; o > 0; o >>= 1)
        vsum += __shfl_xor_sync(0xffffffffu, vsum, o);
    __syncthreads();
    if ((tid & 31) == 0) sred[tid >> 5] = vsum;
    __syncthreads();
    float bsum = 0.f;
    #pragma unroll
    for (int w = 0; w < 8; w++) bsum += sred[w];

    float inv = __frcp_rn(bsum);
    #pragma unroll
    for (int i = 0; i < 8; i++)
        out_w[b * SS + tid + i * 256] = vals[i] * inv;
}

// ---------------------------------------------------------------------------
// K4a: partial context over an S-chunk
// ---------------------------------------------------------------------------
__global__ void __launch_bounds__(128) context_partial_kernel(
        const float* __restrict__ enc,
        const float* __restrict__ w) {
    const int b  = blockIdx.x;
    const int sp = blockIdx.y;
    const int e4 = threadIdx.x << 2;

    const float* wb   = w + b * SS + sp * SCH;
    const float* encb = enc + ((size_t)b * SS + (size_t)sp * SCH) * EH + e4;

    float4 acc = make_float4(0.f, 0.f, 0.f, 0.f);
    #pragma unroll 4
    for (int s = 0; s < SCH; s++) {
        float ws = wb[s];
        float4 ev = *(const float4*)(encb + (size_t)s * EH);
        acc.x += ws * ev.x;
        acc.y += ws * ev.y;
        acc.z += ws * ev.z;
        acc.w += ws * ev.w;
    }
    *(float4*)&g_ctx_part[((size_t)sp * BB + b) * EH + e4] = acc;
}

// ---------------------------------------------------------------------------
// K4b: deterministic reduce of the SPLITS partials into ctx (d_out)
// ---------------------------------------------------------------------------
__global__ void __launch_bounds__(256) context_reduce_kernel(float* __restrict__ ctx) {
    const int i = blockIdx.x * 256 + threadIdx.x;
    float s = 0.f;
    #pragma unroll
    for (int sp = 0; sp < SPLITS; sp++)
        s += g_ctx_part[(size_t)sp * BB * EH + i];
    ctx[i] = s;
}

// ---------------------------------------------------------------------------
extern "C" void kernel_launch(void* const* d_in, const int* in_sizes, int n_in,
                              void* d_out, int out_size) {
    const float* enc   = (const float*)d_in[0];  // [B,S,EH]
    const float* dec   = (const float*)d_in[1];  // [B,EH]
    const float* W_enc = (const float*)d_in[2];  // [AH,EH]
    const float* W_dec = (const float*)d_in[3];  // [AH,EH]
    const float* v     = (const float*)d_in[4];  // [1,AH]

    float* out = (float*)d_out;
    float* out_ctx = out;                 // [B, EH]
    float* out_w   = out + BB * EH;       // [B, S]

    dec_proj_kernel<<<BB, 256>>>(dec, W_dec);

    dim3 g2(SS / 128, BB);
    score_kernel<<<g2, 256>>>(enc, W_enc, v);

    softmax_kernel<<<BB, 256>>>(out_w);

    dim3 g4(BB, SPLITS);
    context_partial_kernel<<<g4, 128>>>(enc, out_w);

    context_reduce_kernel<<<(BB * EH) / 256, 256>>>(out_ctx);
}